// round 4
// baseline (speedup 1.0000x reference)
#include <cuda_runtime.h>
#include <cuda_bf16.h>
#include <cstdint>

#define B_SZ 2
#define T_SZ 2048
#define C_SZ 2048
#define NH 16
#define NKV 4
#define HD 128
#define RMS_EPS 1.1920929e-07f
#define ATT_SCALE 0.08838834764831845f   // 1/sqrt(128)
#define NEG_BIG -1e30f

// ---------------- scratch (static device globals; no allocation) ----------------
__device__ float g_q[(size_t)B_SZ * T_SZ * NH * HD];    // [B*T, 2048]
__device__ float g_k[(size_t)B_SZ * T_SZ * NKV * HD];   // [B*T, 512]
__device__ float g_v[(size_t)B_SZ * T_SZ * NKV * HD];   // [B*T, 512]
__device__ float g_y[(size_t)B_SZ * T_SZ * C_SZ];       // [B*T, 2048]

// ---------------- helpers ---------------------------------------------------------
__device__ __forceinline__ uint32_t f2tf(float f) {
    uint32_t u;
    asm("cvt.rna.tf32.f32 %0, %1;" : "=r"(u) : "f"(f));
    return u;
}

__device__ __forceinline__ void mma_tf32(float* c, const uint32_t* a, const uint32_t* b) {
    asm volatile("mma.sync.aligned.m16n8k8.row.col.f32.tf32.tf32.f32 "
                 "{%0,%1,%2,%3}, {%4,%5,%6,%7}, {%8,%9}, {%0,%1,%2,%3};"
                 : "+f"(c[0]), "+f"(c[1]), "+f"(c[2]), "+f"(c[3])
                 : "r"(a[0]), "r"(a[1]), "r"(a[2]), "r"(a[3]),
                   "r"(b[0]), "r"(b[1]));
}

#define CP_ASYNC16(dst_u32, src_ptr) \
    asm volatile("cp.async.cg.shared.global [%0], [%1], 16;" :: "r"(dst_u32), "l"(src_ptr))
#define CP_COMMIT() asm volatile("cp.async.commit_group;" ::: "memory")
#define CP_WAIT(n)  asm volatile("cp.async.wait_group %0;" :: "n"(n) : "memory")

__device__ __forceinline__ uint32_t smem_u32(const void* p) {
    return (uint32_t)__cvta_generic_to_shared(p);
}

// ---------------- TF32 GEMM, cp.async double-buffered: C = A[M,K] * B[N,K]^T ------
// 128x128 CTA tile, K-chunk 32, 256 threads (8 warps 2x4), warp tile 64x32.
#define GLD 36           // smem row pad (floats): lane bank = (4g+t), conflict-free
#define GTILE (128 * GLD)

__global__ __launch_bounds__(256, 2) void gemm_tf32(const float* __restrict__ A,
                                                    const float* __restrict__ B,
                                                    float* __restrict__ C,
                                                    int M, int N, int K) {
    extern __shared__ float gsm[];
    float* As = gsm;                 // [2][128][36]
    float* Bs = gsm + 2 * GTILE;     // [2][128][36]

    const int tid  = threadIdx.x;
    const int bm   = blockIdx.y * 128;
    const int bn   = blockIdx.x * 128;
    const int warp = tid >> 5;
    const int lane = tid & 31;
    const int wm   = warp >> 2;          // 0..1
    const int wn   = warp & 3;           // 0..3
    const int g    = lane >> 2;          // 0..7
    const int t    = lane & 3;           // 0..3
    const int arow = tid >> 3;           // 0..31
    const int ac4  = (tid & 7) * 4;      // 0,4,...,28

    float acc[4][4][4];
#pragma unroll
    for (int mi = 0; mi < 4; mi++)
#pragma unroll
        for (int ni = 0; ni < 4; ni++)
#pragma unroll
            for (int r = 0; r < 4; r++) acc[mi][ni][r] = 0.f;

    const float* Ag = A + (size_t)(bm + arow) * K + ac4;
    const float* Bg = B + (size_t)(bn + arow) * K + ac4;

    const int nt = K / 32;

    // stage K-chunk kk into buffer buf
    auto stage = [&](int buf, int kk) {
        float* ad = As + buf * GTILE;
        float* bd = Bs + buf * GTILE;
#pragma unroll
        for (int p = 0; p < 4; p++) {
            CP_ASYNC16(smem_u32(ad + (arow + 32 * p) * GLD + ac4), Ag + (size_t)p * 32 * K + kk);
            CP_ASYNC16(smem_u32(bd + (arow + 32 * p) * GLD + ac4), Bg + (size_t)p * 32 * K + kk);
        }
    };

    stage(0, 0);
    CP_COMMIT();

    for (int it = 0; it < nt; it++) {
        const int buf = it & 1;
        if (it + 1 < nt) {
            stage(buf ^ 1, (it + 1) * 32);
            CP_COMMIT();
            CP_WAIT(1);
        } else {
            CP_WAIT(0);
        }
        __syncthreads();

        const float* as = As + buf * GTILE;
        const float* bs = Bs + buf * GTILE;
#pragma unroll
        for (int k8 = 0; k8 < 4; k8++) {
            const int kc = k8 * 8;
            uint32_t af[4][4], bf[4][2];
#pragma unroll
            for (int mi = 0; mi < 4; mi++) {
                const int r = wm * 64 + mi * 16 + g;
                af[mi][0] = f2tf(as[r * GLD + kc + t]);
                af[mi][1] = f2tf(as[(r + 8) * GLD + kc + t]);
                af[mi][2] = f2tf(as[r * GLD + kc + t + 4]);
                af[mi][3] = f2tf(as[(r + 8) * GLD + kc + t + 4]);
            }
#pragma unroll
            for (int ni = 0; ni < 4; ni++) {
                const int c = wn * 32 + ni * 8 + g;
                bf[ni][0] = f2tf(bs[c * GLD + kc + t]);
                bf[ni][1] = f2tf(bs[c * GLD + kc + t + 4]);
            }
#pragma unroll
            for (int mi = 0; mi < 4; mi++)
#pragma unroll
                for (int ni = 0; ni < 4; ni++)
                    mma_tf32(acc[mi][ni], af[mi], bf[ni]);
        }
        __syncthreads();
    }

#pragma unroll
    for (int mi = 0; mi < 4; mi++) {
        const int r = bm + wm * 64 + mi * 16 + g;
#pragma unroll
        for (int ni = 0; ni < 4; ni++) {
            const int c = bn + wn * 32 + ni * 8 + 2 * t;
            *(float2*)&C[(size_t)r * N + c] = make_float2(acc[mi][ni][0], acc[mi][ni][1]);
            *(float2*)&C[(size_t)(r + 8) * N + c] = make_float2(acc[mi][ni][2], acc[mi][ni][3]);
        }
    }
}

// ---------------- RoPE + RMSNorm (in place on q or k buffer) --------------------
__global__ __launch_bounds__(128) void rope_rmsnorm(float* __restrict__ buf,
                                                    const float* __restrict__ cosb,
                                                    const float* __restrict__ sinb,
                                                    int n_head) {
    const int d = threadIdx.x;                 // 0..127
    const int vid = blockIdx.x;                // (b*T+t)*n_head + h
    const int t = (vid / n_head) % T_SZ;
    float* vec = buf + (size_t)vid * HD;

    float xv = vec[d];
    float xo = (d < HD / 2) ? -vec[d + HD / 2] : vec[d - HD / 2];
    float r = xv * cosb[t * HD + d] + xo * sinb[t * HD + d];

    float s = r * r;
#pragma unroll
    for (int off = 16; off > 0; off >>= 1) s += __shfl_xor_sync(0xffffffffu, s, off);
    __shared__ float ws[4];
    const int lane = d & 31, wid = d >> 5;
    if (lane == 0) ws[wid] = s;
    __syncthreads();
    float tot = ws[0] + ws[1] + ws[2] + ws[3];
    float inv = rsqrtf(tot * (1.0f / HD) + RMS_EPS);
    vec[d] = r * inv;
}

// ---------------- flash attention (TF32 MMA, cp.async double-buffered K/V) -------
#define BM 128
#define BN 64
#define SK_LD 132   // banks (4g+t): conflict-free
#define SV_LD 136   // banks (8t+g): conflict-free
#define SP_LD 68
#define SK_TILE (BN * SK_LD)
#define SV_TILE (BN * SV_LD)

__global__ __launch_bounds__(256, 1) void attn_tc(const float* __restrict__ qb,
                                                  const float* __restrict__ kb,
                                                  const float* __restrict__ vb,
                                                  float* __restrict__ yb) {
    extern __shared__ float sm[];
    float* sK = sm;                              // [2][64][132] fp32
    float* sV = sK + 2 * SK_TILE;                // [2][64][136] fp32
    uint32_t* sP = (uint32_t*)(sV + 2 * SV_TILE);  // [128][68] tf32

    const int qt = blockIdx.x;
    const int h  = blockIdx.y;
    const int b  = blockIdx.z;
    const int kvh = h >> 2;
    const int qs = qt * BM;
    const int tid  = threadIdx.x;
    const int w    = tid >> 5;
    const int lane = tid & 31;
    const int g    = lane >> 2;
    const int t    = lane & 3;
    const int w16  = w * 16;

    // ---- load Q fragments into registers (tf32) ----
    uint32_t qa[16][4];
    {
        const float* q0 = qb + (size_t)(b * T_SZ + qs + w16 + g) * (NH * HD) + h * HD;
        const float* q1 = q0 + (size_t)8 * (NH * HD);
#pragma unroll
        for (int kc = 0; kc < 16; kc++) {
            qa[kc][0] = f2tf(q0[kc * 8 + t]);
            qa[kc][1] = f2tf(q1[kc * 8 + t]);
            qa[kc][2] = f2tf(q0[kc * 8 + t + 4]);
            qa[kc][3] = f2tf(q1[kc * 8 + t + 4]);
        }
    }

    float m0 = NEG_BIG, m1 = NEG_BIG, l0 = 0.f, l1 = 0.f;
    float o[16][4];
#pragma unroll
    for (int dt = 0; dt < 16; dt++)
#pragma unroll
        for (int r = 0; r < 4; r++) o[dt][r] = 0.f;

    const int row0 = qs + w16 + g;
    const int row1 = row0 + 8;

    const int srow = tid >> 2;          // 0..63 (staging row)
    const int quad = tid & 3;
    const float* kbase = kb + (size_t)(b * T_SZ) * (NKV * HD) + kvh * HD;
    const float* vbase = vb + (size_t)(b * T_SZ) * (NKV * HD) + kvh * HD;

    auto stage_kv = [&](int buf, int ks) {
        const float* ksrc = kbase + (size_t)(ks + srow) * (NKV * HD);
        const float* vsrc = vbase + (size_t)(ks + srow) * (NKV * HD);
        float* kd = sK + buf * SK_TILE + srow * SK_LD;
        float* vd = sV + buf * SV_TILE + srow * SV_LD;
#pragma unroll
        for (int i = 0; i < 8; i++) {
            const int d4 = quad * 8 + i;
            CP_ASYNC16(smem_u32(kd + d4 * 4), ksrc + d4 * 4);
            CP_ASYNC16(smem_u32(vd + d4 * 4), vsrc + d4 * 4);
        }
    };

    const int nt = (qs + BM) / BN;      // causal tile count

    stage_kv(0, 0);
    CP_COMMIT();

    for (int it = 0; it < nt; it++) {
        const int buf = it & 1;
        const int ks = it * BN;
        if (it + 1 < nt) {
            stage_kv(buf ^ 1, (it + 1) * BN);
            CP_COMMIT();
            CP_WAIT(1);
        } else {
            CP_WAIT(0);
        }
        __syncthreads();

        const float* kt = sK + buf * SK_TILE;
        const float* vt = sV + buf * SV_TILE;

        // ---- S = Q K^T (16 x 64 per warp) ----
        float s[8][4];
#pragma unroll
        for (int nt2 = 0; nt2 < 8; nt2++)
#pragma unroll
            for (int r = 0; r < 4; r++) s[nt2][r] = 0.f;

#pragma unroll
        for (int kc = 0; kc < 16; kc++) {
#pragma unroll
            for (int nt2 = 0; nt2 < 8; nt2++) {
                uint32_t bf[2];
                bf[0] = f2tf(kt[(nt2 * 8 + g) * SK_LD + kc * 8 + t]);
                bf[1] = f2tf(kt[(nt2 * 8 + g) * SK_LD + kc * 8 + t + 4]);
                mma_tf32(s[nt2], qa[kc], bf);
            }
        }

        // ---- online softmax on accumulator fragments ----
        const bool needs_mask = (ks + BN - 1) > (qs + w16);
        float rm0 = NEG_BIG, rm1 = NEG_BIG;
#pragma unroll
        for (int nt2 = 0; nt2 < 8; nt2++) {
#pragma unroll
            for (int ci = 0; ci < 2; ci++) {
                const int col = ks + nt2 * 8 + 2 * t + ci;
                float v0 = s[nt2][ci] * ATT_SCALE;
                float v1 = s[nt2][2 + ci] * ATT_SCALE;
                if (needs_mask) {
                    if (col > row0) v0 = NEG_BIG;
                    if (col > row1) v1 = NEG_BIG;
                }
                s[nt2][ci] = v0;
                s[nt2][2 + ci] = v1;
                rm0 = fmaxf(rm0, v0);
                rm1 = fmaxf(rm1, v1);
            }
        }
        rm0 = fmaxf(rm0, __shfl_xor_sync(0xffffffffu, rm0, 1));
        rm0 = fmaxf(rm0, __shfl_xor_sync(0xffffffffu, rm0, 2));
        rm1 = fmaxf(rm1, __shfl_xor_sync(0xffffffffu, rm1, 1));
        rm1 = fmaxf(rm1, __shfl_xor_sync(0xffffffffu, rm1, 2));

        const float mn0 = fmaxf(m0, rm0);
        const float mn1 = fmaxf(m1, rm1);
        const float corr0 = __expf(m0 - mn0);
        const float corr1 = __expf(m1 - mn1);
        m0 = mn0; m1 = mn1;

        float rs0 = 0.f, rs1 = 0.f;
#pragma unroll
        for (int nt2 = 0; nt2 < 8; nt2++) {
#pragma unroll
            for (int ci = 0; ci < 2; ci++) {
                float p0 = __expf(s[nt2][ci] - mn0);
                float p1 = __expf(s[nt2][2 + ci] - mn1);
                s[nt2][ci] = p0;
                s[nt2][2 + ci] = p1;
                rs0 += p0;
                rs1 += p1;
            }
        }
        rs0 += __shfl_xor_sync(0xffffffffu, rs0, 1);
        rs0 += __shfl_xor_sync(0xffffffffu, rs0, 2);
        rs1 += __shfl_xor_sync(0xffffffffu, rs1, 1);
        rs1 += __shfl_xor_sync(0xffffffffu, rs1, 2);

        l0 = l0 * corr0 + rs0;
        l1 = l1 * corr1 + rs1;

#pragma unroll
        for (int dt = 0; dt < 16; dt++) {
            o[dt][0] *= corr0; o[dt][1] *= corr0;
            o[dt][2] *= corr1; o[dt][3] *= corr1;
        }

        // ---- write P fragments to warp-private rows of sP ----
#pragma unroll
        for (int nt2 = 0; nt2 < 8; nt2++) {
            uint2 p0 = make_uint2(f2tf(s[nt2][0]), f2tf(s[nt2][1]));
            uint2 p1 = make_uint2(f2tf(s[nt2][2]), f2tf(s[nt2][3]));
            *(uint2*)&sP[(w16 + g) * SP_LD + nt2 * 8 + 2 * t] = p0;
            *(uint2*)&sP[(w16 + 8 + g) * SP_LD + nt2 * 8 + 2 * t] = p1;
        }
        __syncwarp();

        // ---- O += P V  (16 x 128 per warp, k = 64 keys) ----
#pragma unroll
        for (int kc = 0; kc < 8; kc++) {
            uint32_t pa[4];
            pa[0] = sP[(w16 + g) * SP_LD + kc * 8 + t];
            pa[1] = sP[(w16 + 8 + g) * SP_LD + kc * 8 + t];
            pa[2] = sP[(w16 + g) * SP_LD + kc * 8 + t + 4];
            pa[3] = sP[(w16 + 8 + g) * SP_LD + kc * 8 + t + 4];
#pragma unroll
            for (int dt = 0; dt < 16; dt++) {
                uint32_t bf[2];
                bf[0] = f2tf(vt[(kc * 8 + t) * SV_LD + dt * 8 + g]);
                bf[1] = f2tf(vt[(kc * 8 + t + 4) * SV_LD + dt * 8 + g]);
                mma_tf32(o[dt], pa, bf);
            }
        }
        __syncthreads();
    }

    // ---- epilogue ----
    const float inv0 = 1.0f / l0;
    const float inv1 = 1.0f / l1;
    float* dst0 = yb + (size_t)(b * T_SZ + row0) * C_SZ + h * HD;
    float* dst1 = yb + (size_t)(b * T_SZ + row1) * C_SZ + h * HD;
#pragma unroll
    for (int dt = 0; dt < 16; dt++) {
        *(float2*)&dst0[dt * 8 + 2 * t] = make_float2(o[dt][0] * inv0, o[dt][1] * inv0);
        *(float2*)&dst1[dt * 8 + 2 * t] = make_float2(o[dt][2] * inv1, o[dt][3] * inv1);
    }
}

// ---------------- launch ---------------------------------------------------------
extern "C" void kernel_launch(void* const* d_in, const int* in_sizes, int n_in,
                              void* d_out, int out_size) {
    const float* x     = (const float*)d_in[0];
    const float* cosb  = (const float*)d_in[1];
    const float* sinb  = (const float*)d_in[2];
    const float* wq    = (const float*)d_in[3];
    const float* wk    = (const float*)d_in[4];
    const float* wv    = (const float*)d_in[5];
    const float* wproj = (const float*)d_in[6];
    float* out = (float*)d_out;

    float *qp, *kp, *vp, *yp;
    cudaGetSymbolAddress((void**)&qp, g_q);
    cudaGetSymbolAddress((void**)&kp, g_k);
    cudaGetSymbolAddress((void**)&vp, g_v);
    cudaGetSymbolAddress((void**)&yp, g_y);

    const int M = B_SZ * T_SZ;   // 4096

    const int gemm_smem = 4 * GTILE * sizeof(float);   // 2 bufs x (A+B) = ~72KB
    cudaFuncSetAttribute(gemm_tf32, cudaFuncAttributeMaxDynamicSharedMemorySize, gemm_smem);

    // QKV projections (TF32 tensor cores, cp.async pipelined)
    gemm_tf32<<<dim3((NH * HD) / 128, M / 128), 256, gemm_smem>>>(x, wq, qp, M, NH * HD, C_SZ);
    gemm_tf32<<<dim3((NKV * HD) / 128, M / 128), 256, gemm_smem>>>(x, wk, kp, M, NKV * HD, C_SZ);
    gemm_tf32<<<dim3((NKV * HD) / 128, M / 128), 256, gemm_smem>>>(x, wv, vp, M, NKV * HD, C_SZ);

    // RoPE + RMSNorm on q and k
    rope_rmsnorm<<<M * NH, 128>>>(qp, cosb, sinb, NH);
    rope_rmsnorm<<<M * NKV, 128>>>(kp, cosb, sinb, NKV);

    // attention (TF32 tensor cores, cp.async double-buffered K/V)
    const int attn_smem = (2 * SK_TILE + 2 * SV_TILE) * sizeof(float) + BM * SP_LD * sizeof(uint32_t);
    cudaFuncSetAttribute(attn_tc, cudaFuncAttributeMaxDynamicSharedMemorySize, attn_smem);
    attn_tc<<<dim3(T_SZ / BM, NH, B_SZ), 256, attn_smem>>>(qp, kp, vp, yp);

    // output projection
    gemm_tf32<<<dim3(C_SZ / 128, M / 128), 256, gemm_smem>>>(yp, wproj, out, M, C_SZ, C_SZ);
}

// round 5
// speedup vs baseline: 1.4937x; 1.4937x over previous
#include <cuda_runtime.h>
#include <cuda_bf16.h>
#include <cstdint>

#define B_SZ 2
#define T_SZ 2048
#define C_SZ 2048
#define NH 16
#define NKV 4
#define HD 128
#define RMS_EPS 1.1920929e-07f
#define ATT_SCALE 0.08838834764831845f   // 1/sqrt(128)
#define NEG_BIG -1e30f

// ---------------- scratch (static device globals; no allocation) ----------------
__device__ float g_q[(size_t)B_SZ * T_SZ * NH * HD];    // [B*T, 2048]
__device__ float g_k[(size_t)B_SZ * T_SZ * NKV * HD];   // [B*T, 512]
__device__ float g_v[(size_t)B_SZ * T_SZ * NKV * HD];   // [B*T, 512]
__device__ float g_y[(size_t)B_SZ * T_SZ * C_SZ];       // [B*T, 2048]

// ---------------- TF32 helpers ---------------------------------------------------
__device__ __forceinline__ uint32_t f2tf(float f) {
    uint32_t u;
    asm("cvt.rna.tf32.f32 %0, %1;" : "=r"(u) : "f"(f));
    return u;
}

__device__ __forceinline__ void mma_tf32(float* c, const uint32_t* a, const uint32_t* b) {
    asm volatile("mma.sync.aligned.m16n8k8.row.col.f32.tf32.tf32.f32 "
                 "{%0,%1,%2,%3}, {%4,%5,%6,%7}, {%8,%9}, {%0,%1,%2,%3};"
                 : "+f"(c[0]), "+f"(c[1]), "+f"(c[2]), "+f"(c[3])
                 : "r"(a[0]), "r"(a[1]), "r"(a[2]), "r"(a[3]),
                   "r"(b[0]), "r"(b[1]));
}

// ---------------- TF32 GEMM: C[M,N] = A[M,K] * B[N,K]^T ---------------------------
// 128x128 CTA tile, K-chunk 32, 256 threads (8 warps 2x4), warp tile 64x32.
// tf32 in smem (cvt once at staging), register prefetch, double-buffered smem
// (one __syncthreads per K-chunk).
#define GLD 36
#define GTILE (128 * GLD)

__global__ __launch_bounds__(256, 2) void gemm_tf32(const float* __restrict__ A,
                                                    const float* __restrict__ B,
                                                    float* __restrict__ C,
                                                    int M, int N, int K) {
    extern __shared__ uint32_t gsm[];
    uint32_t* As = gsm;                 // [2][128][36] tf32
    uint32_t* Bs = gsm + 2 * GTILE;     // [2][128][36] tf32

    const int tid  = threadIdx.x;
    const int bm   = blockIdx.y * 128;
    const int bn   = blockIdx.x * 128;
    const int warp = tid >> 5;
    const int lane = tid & 31;
    const int wm   = warp >> 2;          // 0..1
    const int wn   = warp & 3;           // 0..3
    const int g    = lane >> 2;          // 0..7
    const int t    = lane & 3;           // 0..3
    const int arow = tid >> 3;           // 0..31
    const int ac4  = (tid & 7) * 4;      // 0,4,...,28

    float acc[4][4][4];
#pragma unroll
    for (int mi = 0; mi < 4; mi++)
#pragma unroll
        for (int ni = 0; ni < 4; ni++)
#pragma unroll
            for (int r = 0; r < 4; r++) acc[mi][ni][r] = 0.f;

    const float* Ag = A + (size_t)(bm + arow) * K + ac4;
    const float* Bg = B + (size_t)(bn + arow) * K + ac4;

    float4 ra[4], rb[4];
#pragma unroll
    for (int p = 0; p < 4; p++) {
        ra[p] = *(const float4*)(Ag + (size_t)p * 32 * K);
        rb[p] = *(const float4*)(Bg + (size_t)p * 32 * K);
    }

    // store prefetched regs (cvt to tf32) into buffer buf
    auto sts_tile = [&](int buf) {
        uint32_t* ad = As + buf * GTILE;
        uint32_t* bd = Bs + buf * GTILE;
#pragma unroll
        for (int p = 0; p < 4; p++) {
            uint4 a4 = make_uint4(f2tf(ra[p].x), f2tf(ra[p].y), f2tf(ra[p].z), f2tf(ra[p].w));
            uint4 b4 = make_uint4(f2tf(rb[p].x), f2tf(rb[p].y), f2tf(rb[p].z), f2tf(rb[p].w));
            *(uint4*)&ad[(arow + 32 * p) * GLD + ac4] = a4;
            *(uint4*)&bd[(arow + 32 * p) * GLD + ac4] = b4;
        }
    };

    const int nt = K / 32;
    sts_tile(0);
    __syncthreads();

    for (int it = 0; it < nt; it++) {
        const int buf = it & 1;
        const bool more = (it + 1 < nt);
        if (more) {
            const int kk = (it + 1) * 32;
#pragma unroll
            for (int p = 0; p < 4; p++) {
                ra[p] = *(const float4*)(Ag + (size_t)p * 32 * K + kk);
                rb[p] = *(const float4*)(Bg + (size_t)p * 32 * K + kk);
            }
        }

        const uint32_t* as = As + buf * GTILE;
        const uint32_t* bs = Bs + buf * GTILE;
#pragma unroll
        for (int k8 = 0; k8 < 4; k8++) {
            const int kc = k8 * 8;
            uint32_t af[4][4], bf[4][2];
#pragma unroll
            for (int mi = 0; mi < 4; mi++) {
                const int r = wm * 64 + mi * 16 + g;
                af[mi][0] = as[r * GLD + kc + t];
                af[mi][1] = as[(r + 8) * GLD + kc + t];
                af[mi][2] = as[r * GLD + kc + t + 4];
                af[mi][3] = as[(r + 8) * GLD + kc + t + 4];
            }
#pragma unroll
            for (int ni = 0; ni < 4; ni++) {
                const int c = wn * 32 + ni * 8 + g;
                bf[ni][0] = bs[c * GLD + kc + t];
                bf[ni][1] = bs[c * GLD + kc + t + 4];
            }
#pragma unroll
            for (int mi = 0; mi < 4; mi++)
#pragma unroll
                for (int ni = 0; ni < 4; ni++)
                    mma_tf32(acc[mi][ni], af[mi], bf[ni]);
        }

        if (more) {
            sts_tile(buf ^ 1);   // writes other buffer: no read hazard
            __syncthreads();     // one barrier per chunk
        }
    }

#pragma unroll
    for (int mi = 0; mi < 4; mi++) {
        const int r = bm + wm * 64 + mi * 16 + g;
#pragma unroll
        for (int ni = 0; ni < 4; ni++) {
            const int c = bn + wn * 32 + ni * 8 + 2 * t;
            *(float2*)&C[(size_t)r * N + c] = make_float2(acc[mi][ni][0], acc[mi][ni][1]);
            *(float2*)&C[(size_t)(r + 8) * N + c] = make_float2(acc[mi][ni][2], acc[mi][ni][3]);
        }
    }
}

// ---------------- RoPE + RMSNorm (in place on q or k buffer) --------------------
__global__ __launch_bounds__(128) void rope_rmsnorm(float* __restrict__ buf,
                                                    const float* __restrict__ cosb,
                                                    const float* __restrict__ sinb,
                                                    int n_head) {
    const int d = threadIdx.x;                 // 0..127
    const int vid = blockIdx.x;                // (b*T+t)*n_head + h
    const int t = (vid / n_head) % T_SZ;
    float* vec = buf + (size_t)vid * HD;

    float xv = vec[d];
    float xo = (d < HD / 2) ? -vec[d + HD / 2] : vec[d - HD / 2];
    float r = xv * cosb[t * HD + d] + xo * sinb[t * HD + d];

    float s = r * r;
#pragma unroll
    for (int off = 16; off > 0; off >>= 1) s += __shfl_xor_sync(0xffffffffu, s, off);
    __shared__ float ws[4];
    const int lane = d & 31, wid = d >> 5;
    if (lane == 0) ws[wid] = s;
    __syncthreads();
    float tot = ws[0] + ws[1] + ws[2] + ws[3];
    float inv = rsqrtf(tot * (1.0f / HD) + RMS_EPS);
    vec[d] = r * inv;
}

// ---------------- flash attention (TF32 tensor cores, causal, GQA) ---------------
// BM=128 q rows, BN=64 keys, 8 warps; warp w owns q rows [w*16, w*16+16).
// Q held in registers as mma A-fragments; K/V staged as tf32 (cvt at staging).
#define BM 128
#define BN 64
#define SK_LD 132   // banks (4g+t): conflict-free
#define SV_LD 136   // banks (8t+g): conflict-free
#define SP_LD 68

__global__ __launch_bounds__(256, 1) void attn_tc(const float* __restrict__ qb,
                                                  const float* __restrict__ kb,
                                                  const float* __restrict__ vb,
                                                  float* __restrict__ yb) {
    extern __shared__ uint32_t smu[];
    uint32_t* sK = smu;                       // [64][132]
    uint32_t* sV = sK + BN * SK_LD;           // [64][136]
    uint32_t* sP = sV + BN * SV_LD;           // [128][68]

    // reversed qtile order: heaviest (most KV tiles) CTAs launch first
    const int qt = gridDim.x - 1 - blockIdx.x;
    const int h  = blockIdx.y;
    const int b  = blockIdx.z;
    const int kvh = h >> 2;
    const int qs = qt * BM;
    const int tid  = threadIdx.x;
    const int w    = tid >> 5;
    const int lane = tid & 31;
    const int g    = lane >> 2;
    const int t    = lane & 3;
    const int w16  = w * 16;

    // ---- load Q fragments into registers (tf32) ----
    uint32_t qa[16][4];
    {
        const float* q0 = qb + (size_t)(b * T_SZ + qs + w16 + g) * (NH * HD) + h * HD;
        const float* q1 = q0 + (size_t)8 * (NH * HD);
#pragma unroll
        for (int kc = 0; kc < 16; kc++) {
            qa[kc][0] = f2tf(q0[kc * 8 + t]);
            qa[kc][1] = f2tf(q1[kc * 8 + t]);
            qa[kc][2] = f2tf(q0[kc * 8 + t + 4]);
            qa[kc][3] = f2tf(q1[kc * 8 + t + 4]);
        }
    }

    float m0 = NEG_BIG, m1 = NEG_BIG, l0 = 0.f, l1 = 0.f;
    float o[16][4];
#pragma unroll
    for (int dt = 0; dt < 16; dt++)
#pragma unroll
        for (int r = 0; r < 4; r++) o[dt][r] = 0.f;

    const int row0 = qs + w16 + g;
    const int row1 = row0 + 8;

    const int kend = qs + BM;
    for (int ks = 0; ks < kend; ks += BN) {
        __syncthreads();   // protect sK/sV against previous iteration's readers
        // ---- stage K,V tiles (fp32 -> tf32, once per element) ----
        {
            const int r = tid >> 2;          // 0..63
            const int quad = tid & 3;
            const float* ksrc = kb + (size_t)(b * T_SZ + ks + r) * (NKV * HD) + kvh * HD;
            const float* vsrc = vb + (size_t)(b * T_SZ + ks + r) * (NKV * HD) + kvh * HD;
#pragma unroll
            for (int i = 0; i < 8; i++) {
                const int d4 = quad * 8 + i;
                float4 kf = *(const float4*)(ksrc + d4 * 4);
                float4 vf = *(const float4*)(vsrc + d4 * 4);
                uint4 kt4 = make_uint4(f2tf(kf.x), f2tf(kf.y), f2tf(kf.z), f2tf(kf.w));
                uint4 vt4 = make_uint4(f2tf(vf.x), f2tf(vf.y), f2tf(vf.z), f2tf(vf.w));
                *(uint4*)&sK[r * SK_LD + d4 * 4] = kt4;
                *(uint4*)&sV[r * SV_LD + d4 * 4] = vt4;
            }
        }
        __syncthreads();

        // ---- S = Q K^T (16 x 64 per warp) ----
        float s[8][4];
#pragma unroll
        for (int nt = 0; nt < 8; nt++)
#pragma unroll
            for (int r = 0; r < 4; r++) s[nt][r] = 0.f;

#pragma unroll
        for (int kc = 0; kc < 16; kc++) {
#pragma unroll
            for (int nt = 0; nt < 8; nt++) {
                uint32_t bf[2];
                bf[0] = sK[(nt * 8 + g) * SK_LD + kc * 8 + t];
                bf[1] = sK[(nt * 8 + g) * SK_LD + kc * 8 + t + 4];
                mma_tf32(s[nt], qa[kc], bf);
            }
        }

        // ---- online softmax on accumulator fragments ----
        const bool needs_mask = (ks + BN - 1) > (qs + w16);
        float rm0 = NEG_BIG, rm1 = NEG_BIG;
#pragma unroll
        for (int nt = 0; nt < 8; nt++) {
#pragma unroll
            for (int ci = 0; ci < 2; ci++) {
                const int col = ks + nt * 8 + 2 * t + ci;
                float v0 = s[nt][ci] * ATT_SCALE;
                float v1 = s[nt][2 + ci] * ATT_SCALE;
                if (needs_mask) {
                    if (col > row0) v0 = NEG_BIG;
                    if (col > row1) v1 = NEG_BIG;
                }
                s[nt][ci] = v0;
                s[nt][2 + ci] = v1;
                rm0 = fmaxf(rm0, v0);
                rm1 = fmaxf(rm1, v1);
            }
        }
        rm0 = fmaxf(rm0, __shfl_xor_sync(0xffffffffu, rm0, 1));
        rm0 = fmaxf(rm0, __shfl_xor_sync(0xffffffffu, rm0, 2));
        rm1 = fmaxf(rm1, __shfl_xor_sync(0xffffffffu, rm1, 1));
        rm1 = fmaxf(rm1, __shfl_xor_sync(0xffffffffu, rm1, 2));

        const float mn0 = fmaxf(m0, rm0);
        const float mn1 = fmaxf(m1, rm1);
        const float corr0 = __expf(m0 - mn0);
        const float corr1 = __expf(m1 - mn1);
        m0 = mn0; m1 = mn1;

        float rs0 = 0.f, rs1 = 0.f;
#pragma unroll
        for (int nt = 0; nt < 8; nt++) {
#pragma unroll
            for (int ci = 0; ci < 2; ci++) {
                float p0 = __expf(s[nt][ci] - mn0);
                float p1 = __expf(s[nt][2 + ci] - mn1);
                s[nt][ci] = p0;
                s[nt][2 + ci] = p1;
                rs0 += p0;
                rs1 += p1;
            }
        }
        rs0 += __shfl_xor_sync(0xffffffffu, rs0, 1);
        rs0 += __shfl_xor_sync(0xffffffffu, rs0, 2);
        rs1 += __shfl_xor_sync(0xffffffffu, rs1, 1);
        rs1 += __shfl_xor_sync(0xffffffffu, rs1, 2);

        l0 = l0 * corr0 + rs0;
        l1 = l1 * corr1 + rs1;

#pragma unroll
        for (int dt = 0; dt < 16; dt++) {
            o[dt][0] *= corr0; o[dt][1] *= corr0;
            o[dt][2] *= corr1; o[dt][3] *= corr1;
        }

        // ---- write P fragments to warp-private rows of sP ----
#pragma unroll
        for (int nt = 0; nt < 8; nt++) {
            uint2 p0 = make_uint2(f2tf(s[nt][0]), f2tf(s[nt][1]));
            uint2 p1 = make_uint2(f2tf(s[nt][2]), f2tf(s[nt][3]));
            *(uint2*)&sP[(w16 + g) * SP_LD + nt * 8 + 2 * t] = p0;
            *(uint2*)&sP[(w16 + 8 + g) * SP_LD + nt * 8 + 2 * t] = p1;
        }
        __syncwarp();

        // ---- O += P V  (16 x 128 per warp, k = 64 keys) ----
#pragma unroll
        for (int kc = 0; kc < 8; kc++) {
            uint32_t pa[4];
            pa[0] = sP[(w16 + g) * SP_LD + kc * 8 + t];
            pa[1] = sP[(w16 + 8 + g) * SP_LD + kc * 8 + t];
            pa[2] = sP[(w16 + g) * SP_LD + kc * 8 + t + 4];
            pa[3] = sP[(w16 + 8 + g) * SP_LD + kc * 8 + t + 4];
#pragma unroll
            for (int dt = 0; dt < 16; dt++) {
                uint32_t bf[2];
                bf[0] = sV[(kc * 8 + t) * SV_LD + dt * 8 + g];
                bf[1] = sV[(kc * 8 + t + 4) * SV_LD + dt * 8 + g];
                mma_tf32(o[dt], pa, bf);
            }
        }
    }

    // ---- epilogue ----
    const float inv0 = 1.0f / l0;
    const float inv1 = 1.0f / l1;
    float* dst0 = yb + (size_t)(b * T_SZ + row0) * C_SZ + h * HD;
    float* dst1 = yb + (size_t)(b * T_SZ + row1) * C_SZ + h * HD;
#pragma unroll
    for (int dt = 0; dt < 16; dt++) {
        *(float2*)&dst0[dt * 8 + 2 * t] = make_float2(o[dt][0] * inv0, o[dt][1] * inv0);
        *(float2*)&dst1[dt * 8 + 2 * t] = make_float2(o[dt][2] * inv1, o[dt][3] * inv1);
    }
}

// ---------------- launch ---------------------------------------------------------
extern "C" void kernel_launch(void* const* d_in, const int* in_sizes, int n_in,
                              void* d_out, int out_size) {
    const float* x     = (const float*)d_in[0];
    const float* cosb  = (const float*)d_in[1];
    const float* sinb  = (const float*)d_in[2];
    const float* wq    = (const float*)d_in[3];
    const float* wk    = (const float*)d_in[4];
    const float* wv    = (const float*)d_in[5];
    const float* wproj = (const float*)d_in[6];
    float* out = (float*)d_out;

    float *qp, *kp, *vp, *yp;
    cudaGetSymbolAddress((void**)&qp, g_q);
    cudaGetSymbolAddress((void**)&kp, g_k);
    cudaGetSymbolAddress((void**)&vp, g_v);
    cudaGetSymbolAddress((void**)&yp, g_y);

    const int M = B_SZ * T_SZ;   // 4096

    const int gemm_smem = 4 * GTILE * sizeof(uint32_t);   // 2 bufs x (A+B) = 72KB
    cudaFuncSetAttribute(gemm_tf32, cudaFuncAttributeMaxDynamicSharedMemorySize, gemm_smem);

    // QKV projections (TF32 tensor cores)
    gemm_tf32<<<dim3((NH * HD) / 128, M / 128), 256, gemm_smem>>>(x, wq, qp, M, NH * HD, C_SZ);
    gemm_tf32<<<dim3((NKV * HD) / 128, M / 128), 256, gemm_smem>>>(x, wk, kp, M, NKV * HD, C_SZ);
    gemm_tf32<<<dim3((NKV * HD) / 128, M / 128), 256, gemm_smem>>>(x, wv, vp, M, NKV * HD, C_SZ);

    // RoPE + RMSNorm on q and k
    rope_rmsnorm<<<M * NH, 128>>>(qp, cosb, sinb, NH);
    rope_rmsnorm<<<M * NKV, 128>>>(kp, cosb, sinb, NKV);

    // attention (TF32 tensor cores)
    const int attn_smem = (BN * SK_LD + BN * SV_LD + BM * SP_LD) * sizeof(uint32_t); // ~103KB
    cudaFuncSetAttribute(attn_tc, cudaFuncAttributeMaxDynamicSharedMemorySize, attn_smem);
    attn_tc<<<dim3(T_SZ / BM, NH, B_SZ), 256, attn_smem>>>(qp, kp, vp, yp);

    // output projection
    gemm_tf32<<<dim3(C_SZ / 128, M / 128), 256, gemm_smem>>>(yp, wproj, out, M, C_SZ, C_SZ);
}

// round 6
// speedup vs baseline: 2.5741x; 1.7233x over previous
#include <cuda_runtime.h>
#include <cuda_fp16.h>
#include <cstdint>

#define B_SZ 2
#define T_SZ 2048
#define C_SZ 2048
#define NH 16
#define NKV 4
#define HD 128
#define RMS_EPS 1.1920929e-07f
#define ATT_SCALE 0.08838834764831845f   // 1/sqrt(128)
#define NEG_BIG -1e30f

// ---------------- scratch (static device globals; no allocation) ----------------
__device__ __half g_q[(size_t)B_SZ * T_SZ * NH * HD];           // [B*T][2048] half
__device__ __half g_k[(size_t)B_SZ * T_SZ * NKV * HD];          // [B*T][512] half
__device__ __half g_vt[(size_t)B_SZ * NKV * HD * T_SZ];         // [B][NKV][HD][T] half
__device__ float  g_y[(size_t)B_SZ * T_SZ * C_SZ];              // [B*T][2048] fp32

// ---------------- fp16 mma helpers ------------------------------------------------
__device__ __forceinline__ uint32_t packh2(float lo, float hi) {
    __half2 h = __floats2half2_rn(lo, hi);
    return *(uint32_t*)&h;
}

__device__ __forceinline__ void mma_f16(float* c, const uint32_t* a, const uint32_t* b) {
    asm volatile("mma.sync.aligned.m16n8k16.row.col.f32.f16.f16.f32 "
                 "{%0,%1,%2,%3}, {%4,%5,%6,%7}, {%8,%9}, {%0,%1,%2,%3};"
                 : "+f"(c[0]), "+f"(c[1]), "+f"(c[2]), "+f"(c[3])
                 : "r"(a[0]), "r"(a[1]), "r"(a[2]), "r"(a[3]),
                   "r"(b[0]), "r"(b[1]));
}

// ---------------- FP16 GEMM: C[M,N] = A[M,K] * B[N,K]^T ---------------------------
// 128x128 CTA tile, K-chunk 32, 256 threads (8 warps 2x4), warp tile 64x32.
// Inputs fp32 in global, converted to half2 once at staging. Double-buffered smem.
// MODE 0: fp32 C store.  MODE 1: fused RoPE+RMSNorm -> half C (N-tile == one head).
// MODE 2: half C stored transposed into g_vt [B][NKV][HD][T].
#define GLDW 20                    // smem words (half2) per row; banks 20g+t distinct
#define GTILEW (128 * GLDW)
#define SE_LD 130                  // epilogue fp32 buffer row stride

template <int MODE>
__global__ __launch_bounds__(256, 2) void gemm_f16(const float* __restrict__ A,
                                                   const float* __restrict__ B,
                                                   void* __restrict__ Cv,
                                                   int M, int N, int K,
                                                   const float* __restrict__ cosb,
                                                   const float* __restrict__ sinb) {
    extern __shared__ uint32_t gsm[];
    uint32_t* As = gsm;                  // [2][128][20] half2-words
    uint32_t* Bs = gsm + 2 * GTILEW;     // [2][128][20]

    const int tid  = threadIdx.x;
    const int bm   = blockIdx.y * 128;
    const int bn   = blockIdx.x * 128;
    const int warp = tid >> 5;
    const int lane = tid & 31;
    const int wm   = warp >> 2;          // 0..1
    const int wn   = warp & 3;           // 0..3
    const int g    = lane >> 2;          // 0..7
    const int t    = lane & 3;           // 0..3
    const int arow = tid >> 3;           // 0..31
    const int ac4  = (tid & 7) * 4;      // fp32 col base 0,4,...,28
    const int wix  = ac4 >> 1;           // half2-word index

    float acc[4][4][4];
#pragma unroll
    for (int mi = 0; mi < 4; mi++)
#pragma unroll
        for (int ni = 0; ni < 4; ni++)
#pragma unroll
            for (int r = 0; r < 4; r++) acc[mi][ni][r] = 0.f;

    const float* Ag = A + (size_t)(bm + arow) * K + ac4;
    const float* Bg = B + (size_t)(bn + arow) * K + ac4;

    float4 ra[4], rb[4];
#pragma unroll
    for (int p = 0; p < 4; p++) {
        ra[p] = *(const float4*)(Ag + (size_t)p * 32 * K);
        rb[p] = *(const float4*)(Bg + (size_t)p * 32 * K);
    }

    auto sts_tile = [&](int buf) {
        uint32_t* ad = As + buf * GTILEW;
        uint32_t* bd = Bs + buf * GTILEW;
#pragma unroll
        for (int p = 0; p < 4; p++) {
            uint2 a2 = make_uint2(packh2(ra[p].x, ra[p].y), packh2(ra[p].z, ra[p].w));
            uint2 b2 = make_uint2(packh2(rb[p].x, rb[p].y), packh2(rb[p].z, rb[p].w));
            *(uint2*)&ad[(arow + 32 * p) * GLDW + wix] = a2;
            *(uint2*)&bd[(arow + 32 * p) * GLDW + wix] = b2;
        }
    };

    const int nt = K / 32;
    sts_tile(0);
    __syncthreads();

    for (int it = 0; it < nt; it++) {
        const int buf = it & 1;
        const bool more = (it + 1 < nt);
        if (more) {
            const int kk = (it + 1) * 32;
#pragma unroll
            for (int p = 0; p < 4; p++) {
                ra[p] = *(const float4*)(Ag + (size_t)p * 32 * K + kk);
                rb[p] = *(const float4*)(Bg + (size_t)p * 32 * K + kk);
            }
        }

        const uint32_t* as = As + buf * GTILEW;
        const uint32_t* bs = Bs + buf * GTILEW;
#pragma unroll
        for (int s16 = 0; s16 < 2; s16++) {
            const int kc = s16 * 8;
            uint32_t af[4][4], bf[4][2];
#pragma unroll
            for (int mi = 0; mi < 4; mi++) {
                const int r = wm * 64 + mi * 16 + g;
                af[mi][0] = as[r * GLDW + kc + t];
                af[mi][1] = as[(r + 8) * GLDW + kc + t];
                af[mi][2] = as[r * GLDW + kc + t + 4];
                af[mi][3] = as[(r + 8) * GLDW + kc + t + 4];
            }
#pragma unroll
            for (int ni = 0; ni < 4; ni++) {
                const int c = wn * 32 + ni * 8 + g;
                bf[ni][0] = bs[c * GLDW + kc + t];
                bf[ni][1] = bs[c * GLDW + kc + t + 4];
            }
#pragma unroll
            for (int mi = 0; mi < 4; mi++)
#pragma unroll
                for (int ni = 0; ni < 4; ni++)
                    mma_f16(acc[mi][ni], af[mi], bf[ni]);
        }

        if (more) {
            sts_tile(buf ^ 1);
            __syncthreads();
        }
    }

    // ------------------- epilogues -------------------
    if constexpr (MODE == 0) {
        float* C = (float*)Cv;
#pragma unroll
        for (int mi = 0; mi < 4; mi++) {
            const int r = bm + wm * 64 + mi * 16 + g;
#pragma unroll
            for (int ni = 0; ni < 4; ni++) {
                const int c = bn + wn * 32 + ni * 8 + 2 * t;
                *(float2*)&C[(size_t)r * N + c] = make_float2(acc[mi][ni][0], acc[mi][ni][1]);
                *(float2*)&C[(size_t)(r + 8) * N + c] = make_float2(acc[mi][ni][2], acc[mi][ni][3]);
            }
        }
    } else if constexpr (MODE == 2) {
        // transposed half store into g_vt[B][NKV][HD][T]; N-tile == one kv head
        __half* vt = (__half*)Cv;
        const int kvh = blockIdx.x;
#pragma unroll
        for (int mi = 0; mi < 4; mi++) {
            const int gr0 = bm + wm * 64 + mi * 16 + g;
            const int gr1 = gr0 + 8;
            const int b0v = gr0 >> 11, t0v = gr0 & (T_SZ - 1);
            const int b1v = gr1 >> 11, t1v = gr1 & (T_SZ - 1);
#pragma unroll
            for (int ni = 0; ni < 4; ni++) {
                const int d = wn * 32 + ni * 8 + 2 * t;   // local head dim
                size_t base0 = (((size_t)b0v * NKV + kvh) * HD + d) * T_SZ + t0v;
                size_t base1 = (((size_t)b1v * NKV + kvh) * HD + d) * T_SZ + t1v;
                vt[base0]          = __float2half_rn(acc[mi][ni][0]);
                vt[base0 + T_SZ]   = __float2half_rn(acc[mi][ni][1]);
                vt[base1]          = __float2half_rn(acc[mi][ni][2]);
                vt[base1 + T_SZ]   = __float2half_rn(acc[mi][ni][3]);
            }
        }
    } else {
        // MODE 1: fused RoPE + RMSNorm, half output. N-tile == one head (128 cols).
        __syncthreads();                    // drain all warps' frag reads of gsm
        float* sE = (float*)gsm;            // [128][130] fp32
#pragma unroll
        for (int mi = 0; mi < 4; mi++) {
            const int r = wm * 64 + mi * 16 + g;
#pragma unroll
            for (int ni = 0; ni < 4; ni++) {
                const int c = wn * 32 + ni * 8 + 2 * t;
                *(float2*)&sE[r * SE_LD + c] = make_float2(acc[mi][ni][0], acc[mi][ni][1]);
                *(float2*)&sE[(r + 8) * SE_LD + c] = make_float2(acc[mi][ni][2], acc[mi][ni][3]);
            }
        }
        __syncthreads();

        __half* Ch = (__half*)Cv;
        const int row = tid >> 1;
        const int hf  = tid & 1;
        const int d0  = hf * 64;
        const int gr  = bm + row;
        const int tt  = gr & (T_SZ - 1);
        const float sgn = hf ? 1.f : -1.f;   // rotate_half: d<64 -> -x[d+64]; d>=64 -> x[d-64]

        float rv[64];
        float ss = 0.f;
        const float* erow = sE + row * SE_LD;
        const float* cr = cosb + (size_t)tt * HD + d0;
        const float* sr = sinb + (size_t)tt * HD + d0;
#pragma unroll
        for (int i = 0; i < 64; i += 2) {
            float2 v = *(const float2*)&erow[d0 + i];
            float2 p = *(const float2*)&erow[(d0 ^ 64) + i];
            float2 c2 = *(const float2*)&cr[i];
            float2 s2 = *(const float2*)&sr[i];
            float r0 = v.x * c2.x + sgn * p.x * s2.x;
            float r1 = v.y * c2.y + sgn * p.y * s2.y;
            rv[i] = r0; rv[i + 1] = r1;
            ss += r0 * r0 + r1 * r1;
        }
        ss += __shfl_xor_sync(0xffffffffu, ss, 1);
        const float inv = rsqrtf(ss * (1.0f / HD) + RMS_EPS);

        __half2* dst = (__half2*)(Ch + (size_t)gr * N + bn + d0);
#pragma unroll
        for (int i = 0; i < 64; i += 2) {
            __half2 h = __floats2half2_rn(rv[i] * inv, rv[i + 1] * inv);
            dst[i >> 1] = h;
        }
    }
}

// ---------------- flash attention (fp16 mma, causal, GQA) -------------------------
// BM=128 q rows, BN=64 keys, 8 warps; warp w owns q rows [w*16, w*16+16).
// Q in registers as half2 A-frags; K staged [key][d] half; V staged transposed
// [d][key] half. P goes accumulator->half2 A-frags directly (no smem, no sync).
#define BM 128
#define BN 64
#define AK_LD 68   // words/row of sK: banks 4g+t distinct
#define AV_LD 36   // words/row of sVt: banks 4g+t distinct

__global__ __launch_bounds__(256, 1) void attn_f16(const __half* __restrict__ qb,
                                                   const __half* __restrict__ kb,
                                                   const __half* __restrict__ vtb,
                                                   float* __restrict__ yb) {
    extern __shared__ uint32_t smu[];
    uint32_t* sK  = smu;                     // [64][68]  K rows (keys) x dim
    uint32_t* sVt = sK + BN * AK_LD;         // [128][36] V^T rows (dim) x keys

    const int qt = gridDim.x - 1 - blockIdx.x;   // heavy tiles first
    const int h  = blockIdx.y;
    const int b  = blockIdx.z;
    const int kvh = h >> 2;
    const int qs = qt * BM;
    const int tid  = threadIdx.x;
    const int w    = tid >> 5;
    const int lane = tid & 31;
    const int g    = lane >> 2;
    const int t    = lane & 3;
    const int w16  = w * 16;

    // ---- Q fragments (half2 words straight from global) ----
    uint32_t qa[8][4];
    {
        const uint32_t* q0 = (const uint32_t*)(qb + (size_t)(b * T_SZ + qs + w16 + g) * (NH * HD) + h * HD);
        const uint32_t* q1 = q0 + 8 * (NH * HD / 2);
#pragma unroll
        for (int s16 = 0; s16 < 8; s16++) {
            qa[s16][0] = q0[s16 * 8 + t];
            qa[s16][1] = q1[s16 * 8 + t];
            qa[s16][2] = q0[s16 * 8 + t + 4];
            qa[s16][3] = q1[s16 * 8 + t + 4];
        }
    }

    float m0 = NEG_BIG, m1 = NEG_BIG, l0 = 0.f, l1 = 0.f;
    float o[16][4];
#pragma unroll
    for (int dt = 0; dt < 16; dt++)
#pragma unroll
        for (int r = 0; r < 4; r++) o[dt][r] = 0.f;

    const int row0 = qs + w16 + g;
    const int row1 = row0 + 8;

    // staging indices
    const int kr = tid >> 2, kq = tid & 3;        // K: row 0..63, quarter
    const int vr = tid >> 1, vh = tid & 1;        // Vt: row 0..127, half
    const uint32_t* kbase = (const uint32_t*)(kb) + (size_t)b * T_SZ * (NKV * HD / 2) + kvh * (HD / 2);
    const uint32_t* vbase = (const uint32_t*)(vtb) + (((size_t)b * NKV + kvh) * HD + vr) * (T_SZ / 2);

    const int kend = qs + BM;
    for (int ks = 0; ks < kend; ks += BN) {
        __syncthreads();
        // ---- stage K [64][64w] and Vt [128][32w] ----
        {
            const uint32_t* ksrc = kbase + (size_t)(ks + kr) * (NKV * HD / 2);
#pragma unroll
            for (int i = 0; i < 4; i++) {
                *(uint4*)&sK[kr * AK_LD + kq * 16 + 4 * i] = *(const uint4*)&ksrc[kq * 16 + 4 * i];
            }
            const uint32_t* vsrc = vbase + (ks >> 1);
#pragma unroll
            for (int i = 0; i < 4; i++) {
                *(uint4*)&sVt[vr * AV_LD + vh * 16 + 4 * i] = *(const uint4*)&vsrc[vh * 16 + 4 * i];
            }
        }
        __syncthreads();

        const int lim = qs + w16 + 15 - ks;     // max valid local col for this warp
        if (lim < 0) continue;                   // whole warp-tile masked
        const int ntmax = lim >= 63 ? 8 : ((lim >> 3) + 1);
        const int jmax  = lim >= 63 ? 4 : ((lim >> 4) + 1);

        // ---- S = Q K^T (16 x 64 per warp) ----
        float s[8][4];
#pragma unroll
        for (int nb = 0; nb < 8; nb++)
#pragma unroll
            for (int r = 0; r < 4; r++) s[nb][r] = 0.f;

#pragma unroll
        for (int s16 = 0; s16 < 8; s16++) {
#pragma unroll
            for (int nb = 0; nb < 8; nb++) {
                if (nb < ntmax) {
                    uint32_t bf[2];
                    bf[0] = sK[(nb * 8 + g) * AK_LD + s16 * 8 + t];
                    bf[1] = sK[(nb * 8 + g) * AK_LD + s16 * 8 + t + 4];
                    mma_f16(s[nb], qa[s16], bf);
                }
            }
        }

        // ---- online softmax on accumulator fragments ----
        const bool needs_mask = (ks + BN - 1) > (qs + w16);
        float rm0 = NEG_BIG, rm1 = NEG_BIG;
#pragma unroll
        for (int nb = 0; nb < 8; nb++) {
#pragma unroll
            for (int ci = 0; ci < 2; ci++) {
                const int col = ks + nb * 8 + 2 * t + ci;
                float v0 = s[nb][ci] * ATT_SCALE;
                float v1 = s[nb][2 + ci] * ATT_SCALE;
                if (needs_mask) {
                    if (col > row0) v0 = NEG_BIG;
                    if (col > row1) v1 = NEG_BIG;
                }
                s[nb][ci] = v0;
                s[nb][2 + ci] = v1;
                rm0 = fmaxf(rm0, v0);
                rm1 = fmaxf(rm1, v1);
            }
        }
        rm0 = fmaxf(rm0, __shfl_xor_sync(0xffffffffu, rm0, 1));
        rm0 = fmaxf(rm0, __shfl_xor_sync(0xffffffffu, rm0, 2));
        rm1 = fmaxf(rm1, __shfl_xor_sync(0xffffffffu, rm1, 1));
        rm1 = fmaxf(rm1, __shfl_xor_sync(0xffffffffu, rm1, 2));

        const float mn0 = fmaxf(m0, rm0);
        const float mn1 = fmaxf(m1, rm1);
        const float corr0 = __expf(m0 - mn0);
        const float corr1 = __expf(m1 - mn1);
        m0 = mn0; m1 = mn1;

        float rs0 = 0.f, rs1 = 0.f;
#pragma unroll
        for (int nb = 0; nb < 8; nb++) {
#pragma unroll
            for (int ci = 0; ci < 2; ci++) {
                float p0 = __expf(s[nb][ci] - mn0);
                float p1 = __expf(s[nb][2 + ci] - mn1);
                s[nb][ci] = p0;
                s[nb][2 + ci] = p1;
                rs0 += p0;
                rs1 += p1;
            }
        }
        rs0 += __shfl_xor_sync(0xffffffffu, rs0, 1);
        rs0 += __shfl_xor_sync(0xffffffffu, rs0, 2);
        rs1 += __shfl_xor_sync(0xffffffffu, rs1, 1);
        rs1 += __shfl_xor_sync(0xffffffffu, rs1, 2);

        l0 = l0 * corr0 + rs0;
        l1 = l1 * corr1 + rs1;

#pragma unroll
        for (int dt = 0; dt < 16; dt++) {
            o[dt][0] *= corr0; o[dt][1] *= corr0;
            o[dt][2] *= corr1; o[dt][3] *= corr1;
        }

        // ---- O += P V : P accumulator -> half2 A-frags directly ----
#pragma unroll
        for (int j = 0; j < 4; j++) {
            if (j < jmax) {
                uint32_t pa[4];
                pa[0] = packh2(s[2 * j][0], s[2 * j][1]);
                pa[1] = packh2(s[2 * j][2], s[2 * j][3]);
                pa[2] = packh2(s[2 * j + 1][0], s[2 * j + 1][1]);
                pa[3] = packh2(s[2 * j + 1][2], s[2 * j + 1][3]);
#pragma unroll
                for (int dt = 0; dt < 16; dt++) {
                    uint32_t bf[2];
                    bf[0] = sVt[(dt * 8 + g) * AV_LD + j * 8 + t];
                    bf[1] = sVt[(dt * 8 + g) * AV_LD + j * 8 + t + 4];
                    mma_f16(o[dt], pa, bf);
                }
            }
        }
    }

    // ---- epilogue ----
    const float inv0 = 1.0f / l0;
    const float inv1 = 1.0f / l1;
    float* dst0 = yb + (size_t)(b * T_SZ + row0) * C_SZ + h * HD;
    float* dst1 = yb + (size_t)(b * T_SZ + row1) * C_SZ + h * HD;
#pragma unroll
    for (int dt = 0; dt < 16; dt++) {
        *(float2*)&dst0[dt * 8 + 2 * t] = make_float2(o[dt][0] * inv0, o[dt][1] * inv0);
        *(float2*)&dst1[dt * 8 + 2 * t] = make_float2(o[dt][2] * inv1, o[dt][3] * inv1);
    }
}

// ---------------- launch ---------------------------------------------------------
extern "C" void kernel_launch(void* const* d_in, const int* in_sizes, int n_in,
                              void* d_out, int out_size) {
    const float* x     = (const float*)d_in[0];
    const float* cosb  = (const float*)d_in[1];
    const float* sinb  = (const float*)d_in[2];
    const float* wq    = (const float*)d_in[3];
    const float* wk    = (const float*)d_in[4];
    const float* wv    = (const float*)d_in[5];
    const float* wproj = (const float*)d_in[6];
    float* out = (float*)d_out;

    __half *qp, *kp, *vtp;
    float *yp;
    cudaGetSymbolAddress((void**)&qp,  g_q);
    cudaGetSymbolAddress((void**)&kp,  g_k);
    cudaGetSymbolAddress((void**)&vtp, g_vt);
    cudaGetSymbolAddress((void**)&yp,  g_y);

    const int M = B_SZ * T_SZ;   // 4096

    const int smem_plain = 4 * GTILEW * sizeof(uint32_t);           // 40960
    const int smem_rope  = 128 * SE_LD * sizeof(float);             // 66560 (> staging)
    cudaFuncSetAttribute(gemm_f16<0>, cudaFuncAttributeMaxDynamicSharedMemorySize, smem_plain);
    cudaFuncSetAttribute(gemm_f16<1>, cudaFuncAttributeMaxDynamicSharedMemorySize, smem_rope);
    cudaFuncSetAttribute(gemm_f16<2>, cudaFuncAttributeMaxDynamicSharedMemorySize, smem_plain);

    // QKV projections; q/k get fused RoPE+RMSNorm (half out), v stored transposed half
    gemm_f16<1><<<dim3((NH * HD) / 128, M / 128), 256, smem_rope>>>(
        x, wq, (void*)qp, M, NH * HD, C_SZ, cosb, sinb);
    gemm_f16<1><<<dim3((NKV * HD) / 128, M / 128), 256, smem_rope>>>(
        x, wk, (void*)kp, M, NKV * HD, C_SZ, cosb, sinb);
    gemm_f16<2><<<dim3((NKV * HD) / 128, M / 128), 256, smem_plain>>>(
        x, wv, (void*)vtp, M, NKV * HD, C_SZ, nullptr, nullptr);

    // attention
    const int attn_smem = (BN * AK_LD + BM * AV_LD) * sizeof(uint32_t);  // 35840
    cudaFuncSetAttribute(attn_f16, cudaFuncAttributeMaxDynamicSharedMemorySize, attn_smem);
    attn_f16<<<dim3(T_SZ / BM, NH, B_SZ), 256, attn_smem>>>(qp, kp, vtp, yp);

    // output projection (fp32 out)
    gemm_f16<0><<<dim3(C_SZ / 128, M / 128), 256, smem_plain>>>(
        yp, wproj, (void*)out, M, C_SZ, C_SZ, nullptr, nullptr);
}